// round 13
// baseline (speedup 1.0000x reference)
#include <cuda_runtime.h>

#define MAXN 20000
#define DIN  128
#define DHID 256
#define DDNS 128
#define NBLK 304          // 152 SMs x 2 CTAs -> fully resident
#define NTHR 256
#define REP  4            // accumulator replication factor (measured optimum)

// Persistent scratch. RED accumulators are zero at module load; each run
// re-zeroes what it dirties AFTER last consumption -> replays see clean state.
__device__ float  g_de[REP][MAXN];      // RED: degree (replicated)
__device__ float  g_se[REP][MAXN];      // RED: s edge part (replicated)
__device__ float  g_te[REP][MAXN];      // RED: t edge part (replicated)
__device__ float  g_di[MAXN];           // plain stores (N1)
__device__ float  g_q [MAXN];           // plain stores (N2)
__device__ float2 g_coef[MAXN];         // plain stores (N2)
__device__ float  g_ypart[NBLK][DIN];   // plain stores (P4)
__device__ float  g_sum_s;              // RED (N2), zeroed by k_zf
__device__ float  g_u[DHID];            // RED, zeroed by k_zf
__device__ float  g_g[DHID];            // RED, zeroed by k_zf
__device__ float  g_z[DDNS];            // RED, zeroed by k_zf
__device__ unsigned g_count;            // barrier count (self-resetting)
__device__ volatile unsigned g_gen;     // barrier generation (monotonic ok)
__device__ volatile unsigned g_c5, g_c7;  // tail counters, zeroed by k_zf

// Grid barrier: arrival via one atomic per CTA; WAIT is a volatile load spin
// (L2 read, no RMW serialization). All NBLK CTAs resident by construction.
__device__ __forceinline__ void grid_sync() {
    __syncthreads();
    if (threadIdx.x == 0) {
        unsigned gen = g_gen;
        __threadfence();
        if (atomicAdd(&g_count, 1u) == NBLK - 1u) {
            g_count = 0u;
            __threadfence();
            g_gen = gen + 1u;                  // volatile release store
        } else {
            while (g_gen == gen) __nanosleep(32);
            __threadfence();
        }
    }
    __syncthreads();
}

__device__ __forceinline__ void tail_arrive(volatile unsigned* c) {
    __syncthreads();
    if (threadIdx.x == 0) { __threadfence(); atomicAdd((unsigned*)c, 1u); }
}
__device__ __forceinline__ void tail_wait(volatile unsigned* c, unsigned target) {
    if (threadIdx.x == 0) {
        while (*c < target) __nanosleep(32);
        __threadfence();
    }
    __syncthreads();
}

// ---------------------------------------------------------------------------
__global__ void __launch_bounds__(NTHR, 2)
k_main(const float* __restrict__ X,
       const int* __restrict__ row, const int* __restrict__ col,
       const float* __restrict__ w, int e, int n, int chunk) {
    const int tid    = threadIdx.x;
    const int bid    = blockIdx.x;
    const int rep    = bid & (REP - 1);
    const int t0     = bid * NTHR + tid;
    const int stride = NBLK * NTHR;

    __shared__ float st[128];
    __shared__ float sacc[2][DIN];
    __shared__ float sred[8];

    // ---- P1: de[rep][c] += w ----
    for (int i = t0; i < e; i += stride)
        atomicAdd(&g_de[rep][col[i]], w[i]);
    grid_sync();

    // ---- N1: di = rsqrt(1 + sum(de)); zero de replicas ----
    for (int i = t0; i < n; i += stride) {
        float de = 0.0f;
        #pragma unroll
        for (int r = 0; r < REP; r++) { de += g_de[r][i]; g_de[r][i] = 0.0f; }
        g_di[i] = rsqrtf(1.0f + de);
    }
    grid_sync();

    // ---- P2: se[rep][r] += w * di[c]  (unroll 2 for MLP) ----
    {
        int i = t0;
        for (; i + stride < e; i += 2 * stride) {
            int   c0 = col[i],          c1 = col[i + stride];
            int   r0 = row[i],          r1 = row[i + stride];
            float w0 = w[i],            w1 = w[i + stride];
            float d0 = __ldg(&g_di[c0]);
            float d1 = __ldg(&g_di[c1]);
            atomicAdd(&g_se[rep][r0], w0 * d0);
            atomicAdd(&g_se[rep][r1], w1 * d1);
        }
        if (i < e)
            atomicAdd(&g_se[rep][row[i]], w[i] * __ldg(&g_di[col[i]]));
    }
    grid_sync();

    // ---- N2: s = di*se + di^2; q = di*s; coef = (di^2*s, di); sum_s;
    //      zero se replicas ----
    {
        float ssum = 0.0f;
        for (int i = t0; i < n; i += stride) {
            float se = 0.0f;
            #pragma unroll
            for (int r = 0; r < REP; r++) { se += g_se[r][i]; g_se[r][i] = 0.0f; }
            float di = g_di[i];
            float s  = di * se + di * di;
            g_q[i]    = di * s;
            g_coef[i] = make_float2(di * di * s, di);
            ssum += s;
        }
        int lane = tid & 31, wd = tid >> 5;
        #pragma unroll
        for (int o = 16; o > 0; o >>= 1) ssum += __shfl_down_sync(0xffffffffu, ssum, o);
        if (lane == 0) sred[wd] = ssum;
        __syncthreads();
        if (wd == 0) {
            float v = (lane < 8) ? sred[lane] : 0.0f;
            #pragma unroll
            for (int o = 4; o > 0; o >>= 1) v += __shfl_down_sync(0xffffffffu, v, o);
            if (lane == 0 && v != 0.0f) atomicAdd(&g_sum_s, v);
        }
    }
    grid_sync();

    // ---- P3: te[rep][r] += w * q[c]  (unroll 2) ----
    {
        int i = t0;
        for (; i + stride < e; i += 2 * stride) {
            int   c0 = col[i],          c1 = col[i + stride];
            int   r0 = row[i],          r1 = row[i + stride];
            float w0 = w[i],            w1 = w[i + stride];
            float q0 = __ldg(&g_q[c0]);
            float q1 = __ldg(&g_q[c1]);
            atomicAdd(&g_te[rep][r0], w0 * q0);
            atomicAdd(&g_te[rep][r1], w1 * q1);
        }
        if (i < e)
            atomicAdd(&g_te[rep][row[i]], w[i] * __ldg(&g_q[col[i]]));
    }
    grid_sync();

    // ---- P4: y_part = X^T t over this block's rows; zero te replicas ----
    {
        const int d    = tid & 127;
        const int half = tid >> 7;
        const int start = bid * chunk;
        const int end   = min(n, start + chunk);

        float acc = 0.0f;
        for (int base = start; base < end; base += 128) {
            int m = min(128, end - base);
            __syncthreads();
            if (tid < m) {
                int r = base + tid;
                float te = 0.0f;
                #pragma unroll
                for (int k = 0; k < REP; k++) { te += g_te[k][r]; g_te[k][r] = 0.0f; }
                float2 cf = g_coef[r];
                st[tid] = cf.y * te + cf.x;
            }
            __syncthreads();
            #pragma unroll 8
            for (int k = half; k < m; k += 2)
                acc += st[k] * __ldg(X + (size_t)(base + k) * DIN + d);
        }
        sacc[half][d] = acc;
        __syncthreads();
        if (tid < DIN)
            g_ypart[bid][tid] = sacc[0][tid] + sacc[1][tid];
    }
}

// ---------------------------------------------------------------------------
// k_ug (32 blocks x 256): blocks 0..15 do u[j] = sum_d y[d]*W1[d,j];
// internal counter; then all 32 blocks do g[j] += sum_k (u[k]+ss*b1[k])*W2[k,j].
__global__ void __launch_bounds__(256) k_ug(const float* __restrict__ W1,
                                            const float* __restrict__ W2,
                                            const float* __restrict__ b1) {
    __shared__ float svec[8];
    int tid = threadIdx.x;
    int bid = blockIdx.x;
    int lane = tid & 31, wd = tid >> 5;

    if (bid < 16) {
        int d0 = bid * 8;
        {
            float v = 0.0f;
            for (int b = lane; b < NBLK; b += 32) v += g_ypart[b][d0 + wd];
            #pragma unroll
            for (int o = 16; o > 0; o >>= 1) v += __shfl_down_sync(0xffffffffu, v, o);
            if (lane == 0) svec[wd] = v;
        }
        __syncthreads();
        float p = 0.0f;
        #pragma unroll
        for (int d = 0; d < 8; d++)
            p += svec[d] * __ldg(&W1[(d0 + d) * DHID + tid]);
        atomicAdd(&g_u[tid], p);
        tail_arrive(&g_c5);
    }
    tail_wait(&g_c5, 16);
    __syncthreads();

    int k0 = bid * 8;
    if (tid < 8) svec[tid] = g_u[k0 + tid] + g_sum_s * __ldg(&b1[k0 + tid]);
    __syncthreads();
    float p = 0.0f;
    #pragma unroll
    for (int k = 0; k < 8; k++)
        p += svec[k] * __ldg(&W2[(k0 + k) * DHID + tid]);
    atomicAdd(&g_g[tid], p);
}

// k_zf (32 blocks x 128): z-accum; counter; block 0 does relu+logits+softmax
// and re-zeroes all small scratch + counters for the next replay.
__global__ void __launch_bounds__(128) k_zf(const float* __restrict__ Wd1,
                                            const float* __restrict__ b2,
                                            const float* __restrict__ bd1,
                                            const float* __restrict__ Wd2,
                                            const float* __restrict__ bd2,
                                            float* __restrict__ out, float invn) {
    __shared__ float svec[8];
    __shared__ float sp0[4], sp1[4];
    int tid = threadIdx.x;
    int bid = blockIdx.x;
    int lane = tid & 31, wd = tid >> 5;

    {
        int j0 = bid * 8;
        if (tid < 8) svec[tid] = g_g[j0 + tid] * invn + __ldg(&b2[j0 + tid]);
        __syncthreads();
        float p = 0.0f;
        #pragma unroll
        for (int j = 0; j < 8; j++)
            p += svec[j] * __ldg(&Wd1[(j0 + j) * DDNS + tid]);
        atomicAdd(&g_z[tid], p);
    }
    tail_arrive(&g_c7);
    if (bid >= 1) return;
    tail_wait(&g_c7, 32);

    {
        float zr = g_z[tid] + bd1[tid];
        g_z[tid] = 0.0f;
        float z  = zr > 0.0f ? zr : 0.0f;
        float p0 = z * __ldg(&Wd2[tid * 2 + 0]);
        float p1 = z * __ldg(&Wd2[tid * 2 + 1]);
        #pragma unroll
        for (int o = 16; o > 0; o >>= 1) {
            p0 += __shfl_down_sync(0xffffffffu, p0, o);
            p1 += __shfl_down_sync(0xffffffffu, p1, o);
        }
        if (lane == 0) { sp0[wd] = p0; sp1[wd] = p1; }
    }
    g_u[tid] = 0.0f; g_u[tid + 128] = 0.0f;
    g_g[tid] = 0.0f; g_g[tid + 128] = 0.0f;
    __syncthreads();
    if (tid == 0) {
        float l0 = bd2[0] + sp0[0] + sp0[1] + sp0[2] + sp0[3];
        float l1 = bd2[1] + sp1[0] + sp1[1] + sp1[2] + sp1[3];
        float m  = fmaxf(l0, l1);
        float e0 = __expf(l0 - m);
        float e1 = __expf(l1 - m);
        float inv = 1.0f / (e0 + e1);
        out[0] = e0 * inv;
        out[1] = e1 * inv;
        g_sum_s = 0.0f;
        g_c5 = 0u; g_c7 = 0u;
    }
}

// ---------------------------------------------------------------------------
extern "C" void kernel_launch(void* const* d_in, const int* in_sizes, int n_in,
                              void* d_out, int out_size) {
    const float* X   = (const float*)d_in[0];
    const int*   ei  = (const int*)  d_in[1];
    const float* w   = (const float*)d_in[2];
    const float* W1  = (const float*)d_in[3];
    const float* b1  = (const float*)d_in[4];
    const float* W2  = (const float*)d_in[5];
    const float* b2  = (const float*)d_in[6];
    const float* Wd1 = (const float*)d_in[7];
    const float* bd1 = (const float*)d_in[8];
    const float* Wd2 = (const float*)d_in[9];
    const float* bd2 = (const float*)d_in[10];
    float* out = (float*)d_out;

    int n = in_sizes[0] / DIN;        // 20000
    int e = in_sizes[2];              // 640000
    const int* row = ei;
    const int* col = ei + e;
    int chunk = (n + NBLK - 1) / NBLK;

    k_main<<<NBLK, NTHR>>>(X, row, col, w, e, n, chunk);
    k_ug  <<<32,   256>>>(W1, W2, b1);
    k_zf  <<<32,   128>>>(Wd1, b2, bd1, Wd2, bd2, out, 1.0f / (float)n);
}

// round 14
// speedup vs baseline: 1.0137x; 1.0137x over previous
#include <cuda_runtime.h>

#define MAXN 20000
#define DIN  128
#define DHID 256
#define DDNS 128
#define NBLK 304          // 152 SMs x 2 CTAs -> fully resident
#define NTHR 256
#define REP  8            // accumulator replication factor (R11-measured best)

// Persistent scratch. RED accumulators are zero at module load; each run
// re-zeroes what it dirties AFTER last consumption -> replays see clean state.
__device__ float  g_de[REP][MAXN];      // RED: degree (replicated)
__device__ float  g_se[REP][MAXN];      // RED: s edge part (replicated)
__device__ float  g_te[REP][MAXN];      // RED: t edge part (replicated)
__device__ float  g_di[MAXN];           // plain stores (N1)
__device__ float  g_q [MAXN];           // plain stores (N2)
__device__ float2 g_coef[MAXN];         // plain stores (N2)
__device__ float  g_ypart[NBLK][DIN];   // plain stores (P4)
__device__ float  g_sum_s;              // RED (N2), zeroed by k_zf
__device__ float  g_u[DHID];            // RED, zeroed by k_zf
__device__ float  g_g[DHID];            // RED, zeroed by k_zf
__device__ float  g_z[DDNS];            // RED, zeroed by k_zf
__device__ unsigned g_count;            // barrier count (self-resetting)
__device__ volatile unsigned g_gen;     // barrier generation (monotonic ok)
__device__ volatile unsigned g_c5, g_c7;  // tail counters, zeroed by k_zf

// Grid barrier: arrival via one atomic per CTA; WAIT is a volatile load spin
// (L2 read, no RMW serialization). All NBLK CTAs resident by construction.
__device__ __forceinline__ void grid_sync() {
    __syncthreads();
    if (threadIdx.x == 0) {
        unsigned gen = g_gen;
        __threadfence();
        if (atomicAdd(&g_count, 1u) == NBLK - 1u) {
            g_count = 0u;
            __threadfence();
            g_gen = gen + 1u;                  // volatile release store
        } else {
            while (g_gen == gen) __nanosleep(32);
            __threadfence();
        }
    }
    __syncthreads();
}

__device__ __forceinline__ void tail_arrive(volatile unsigned* c) {
    __syncthreads();
    if (threadIdx.x == 0) { __threadfence(); atomicAdd((unsigned*)c, 1u); }
}
__device__ __forceinline__ void tail_wait(volatile unsigned* c, unsigned target) {
    if (threadIdx.x == 0) {
        while (*c < target) __nanosleep(32);
        __threadfence();
    }
    __syncthreads();
}

// ---------------------------------------------------------------------------
__global__ void __launch_bounds__(NTHR, 2)
k_main(const float* __restrict__ X,
       const int* __restrict__ row, const int* __restrict__ col,
       const float* __restrict__ w, int e, int n, int chunk) {
    const int tid    = threadIdx.x;
    const int bid    = blockIdx.x;
    const int rep    = bid & (REP - 1);
    const int t0     = bid * NTHR + tid;
    const int stride = NBLK * NTHR;

    __shared__ float st[128];
    __shared__ float sacc[2][DIN];
    __shared__ float sred[8];

    // ---- P1: de[rep][c] += w  (unroll 4: independent RED chains) ----
    {
        int i = t0;
        for (; i + 3 * stride < e; i += 4 * stride) {
            int   c0 = col[i],              c1 = col[i + stride];
            int   c2 = col[i + 2 * stride], c3 = col[i + 3 * stride];
            float w0 = w[i],                w1 = w[i + stride];
            float w2 = w[i + 2 * stride],   w3 = w[i + 3 * stride];
            atomicAdd(&g_de[rep][c0], w0);
            atomicAdd(&g_de[rep][c1], w1);
            atomicAdd(&g_de[rep][c2], w2);
            atomicAdd(&g_de[rep][c3], w3);
        }
        for (; i < e; i += stride)
            atomicAdd(&g_de[rep][col[i]], w[i]);
    }
    grid_sync();

    // ---- N1: di = rsqrt(1 + sum(de)); zero de replicas ----
    for (int i = t0; i < n; i += stride) {
        float de = 0.0f;
        #pragma unroll
        for (int r = 0; r < REP; r++) { de += g_de[r][i]; g_de[r][i] = 0.0f; }
        g_di[i] = rsqrtf(1.0f + de);
    }
    grid_sync();

    // ---- P2: se[rep][r] += w * di[c]  (unroll 4: 4 gathers + 4 REDs in flight) ----
    {
        int i = t0;
        for (; i + 3 * stride < e; i += 4 * stride) {
            int   c0 = col[i],              c1 = col[i + stride];
            int   c2 = col[i + 2 * stride], c3 = col[i + 3 * stride];
            int   r0 = row[i],              r1 = row[i + stride];
            int   r2 = row[i + 2 * stride], r3 = row[i + 3 * stride];
            float w0 = w[i],                w1 = w[i + stride];
            float w2 = w[i + 2 * stride],   w3 = w[i + 3 * stride];
            float d0 = __ldg(&g_di[c0]);
            float d1 = __ldg(&g_di[c1]);
            float d2 = __ldg(&g_di[c2]);
            float d3 = __ldg(&g_di[c3]);
            atomicAdd(&g_se[rep][r0], w0 * d0);
            atomicAdd(&g_se[rep][r1], w1 * d1);
            atomicAdd(&g_se[rep][r2], w2 * d2);
            atomicAdd(&g_se[rep][r3], w3 * d3);
        }
        for (; i < e; i += stride)
            atomicAdd(&g_se[rep][row[i]], w[i] * __ldg(&g_di[col[i]]));
    }
    grid_sync();

    // ---- N2: s = di*se + di^2; q = di*s; coef = (di^2*s, di); sum_s;
    //      zero se replicas ----
    {
        float ssum = 0.0f;
        for (int i = t0; i < n; i += stride) {
            float se = 0.0f;
            #pragma unroll
            for (int r = 0; r < REP; r++) { se += g_se[r][i]; g_se[r][i] = 0.0f; }
            float di = g_di[i];
            float s  = di * se + di * di;
            g_q[i]    = di * s;
            g_coef[i] = make_float2(di * di * s, di);
            ssum += s;
        }
        int lane = tid & 31, wd = tid >> 5;
        #pragma unroll
        for (int o = 16; o > 0; o >>= 1) ssum += __shfl_down_sync(0xffffffffu, ssum, o);
        if (lane == 0) sred[wd] = ssum;
        __syncthreads();
        if (wd == 0) {
            float v = (lane < 8) ? sred[lane] : 0.0f;
            #pragma unroll
            for (int o = 4; o > 0; o >>= 1) v += __shfl_down_sync(0xffffffffu, v, o);
            if (lane == 0 && v != 0.0f) atomicAdd(&g_sum_s, v);
        }
    }
    grid_sync();

    // ---- P3: te[rep][r] += w * q[c]  (unroll 4) ----
    {
        int i = t0;
        for (; i + 3 * stride < e; i += 4 * stride) {
            int   c0 = col[i],              c1 = col[i + stride];
            int   c2 = col[i + 2 * stride], c3 = col[i + 3 * stride];
            int   r0 = row[i],              r1 = row[i + stride];
            int   r2 = row[i + 2 * stride], r3 = row[i + 3 * stride];
            float w0 = w[i],                w1 = w[i + stride];
            float w2 = w[i + 2 * stride],   w3 = w[i + 3 * stride];
            float q0 = __ldg(&g_q[c0]);
            float q1 = __ldg(&g_q[c1]);
            float q2 = __ldg(&g_q[c2]);
            float q3 = __ldg(&g_q[c3]);
            atomicAdd(&g_te[rep][r0], w0 * q0);
            atomicAdd(&g_te[rep][r1], w1 * q1);
            atomicAdd(&g_te[rep][r2], w2 * q2);
            atomicAdd(&g_te[rep][r3], w3 * q3);
        }
        for (; i < e; i += stride)
            atomicAdd(&g_te[rep][row[i]], w[i] * __ldg(&g_q[col[i]]));
    }
    grid_sync();

    // ---- P4: y_part = X^T t over this block's rows; zero te replicas ----
    {
        const int d    = tid & 127;
        const int half = tid >> 7;
        const int start = bid * chunk;
        const int end   = min(n, start + chunk);

        float acc = 0.0f;
        for (int base = start; base < end; base += 128) {
            int m = min(128, end - base);
            __syncthreads();
            if (tid < m) {
                int r = base + tid;
                float te = 0.0f;
                #pragma unroll
                for (int k = 0; k < REP; k++) { te += g_te[k][r]; g_te[k][r] = 0.0f; }
                float2 cf = g_coef[r];
                st[tid] = cf.y * te + cf.x;
            }
            __syncthreads();
            #pragma unroll 8
            for (int k = half; k < m; k += 2)
                acc += st[k] * __ldg(X + (size_t)(base + k) * DIN + d);
        }
        sacc[half][d] = acc;
        __syncthreads();
        if (tid < DIN)
            g_ypart[bid][tid] = sacc[0][tid] + sacc[1][tid];
    }
}

// ---------------------------------------------------------------------------
// k_ug (32 blocks x 256): blocks 0..15 do u[j] = sum_d y[d]*W1[d,j];
// internal counter; then all 32 blocks do g[j] += sum_k (u[k]+ss*b1[k])*W2[k,j].
__global__ void __launch_bounds__(256) k_ug(const float* __restrict__ W1,
                                            const float* __restrict__ W2,
                                            const float* __restrict__ b1) {
    __shared__ float svec[8];
    int tid = threadIdx.x;
    int bid = blockIdx.x;
    int lane = tid & 31, wd = tid >> 5;

    if (bid < 16) {
        int d0 = bid * 8;
        {
            float v = 0.0f;
            for (int b = lane; b < NBLK; b += 32) v += g_ypart[b][d0 + wd];
            #pragma unroll
            for (int o = 16; o > 0; o >>= 1) v += __shfl_down_sync(0xffffffffu, v, o);
            if (lane == 0) svec[wd] = v;
        }
        __syncthreads();
        float p = 0.0f;
        #pragma unroll
        for (int d = 0; d < 8; d++)
            p += svec[d] * __ldg(&W1[(d0 + d) * DHID + tid]);
        atomicAdd(&g_u[tid], p);
        tail_arrive(&g_c5);
    }
    tail_wait(&g_c5, 16);
    __syncthreads();

    int k0 = bid * 8;
    if (tid < 8) svec[tid] = g_u[k0 + tid] + g_sum_s * __ldg(&b1[k0 + tid]);
    __syncthreads();
    float p = 0.0f;
    #pragma unroll
    for (int k = 0; k < 8; k++)
        p += svec[k] * __ldg(&W2[(k0 + k) * DHID + tid]);
    atomicAdd(&g_g[tid], p);
}

// k_zf (32 blocks x 128): z-accum; counter; block 0 does relu+logits+softmax
// and re-zeroes all small scratch + counters for the next replay.
__global__ void __launch_bounds__(128) k_zf(const float* __restrict__ Wd1,
                                            const float* __restrict__ b2,
                                            const float* __restrict__ bd1,
                                            const float* __restrict__ Wd2,
                                            const float* __restrict__ bd2,
                                            float* __restrict__ out, float invn) {
    __shared__ float svec[8];
    __shared__ float sp0[4], sp1[4];
    int tid = threadIdx.x;
    int bid = blockIdx.x;
    int lane = tid & 31, wd = tid >> 5;

    {
        int j0 = bid * 8;
        if (tid < 8) svec[tid] = g_g[j0 + tid] * invn + __ldg(&b2[j0 + tid]);
        __syncthreads();
        float p = 0.0f;
        #pragma unroll
        for (int j = 0; j < 8; j++)
            p += svec[j] * __ldg(&Wd1[(j0 + j) * DDNS + tid]);
        atomicAdd(&g_z[tid], p);
    }
    tail_arrive(&g_c7);
    if (bid >= 1) return;
    tail_wait(&g_c7, 32);

    {
        float zr = g_z[tid] + bd1[tid];
        g_z[tid] = 0.0f;
        float z  = zr > 0.0f ? zr : 0.0f;
        float p0 = z * __ldg(&Wd2[tid * 2 + 0]);
        float p1 = z * __ldg(&Wd2[tid * 2 + 1]);
        #pragma unroll
        for (int o = 16; o > 0; o >>= 1) {
            p0 += __shfl_down_sync(0xffffffffu, p0, o);
            p1 += __shfl_down_sync(0xffffffffu, p1, o);
        }
        if (lane == 0) { sp0[wd] = p0; sp1[wd] = p1; }
    }
    g_u[tid] = 0.0f; g_u[tid + 128] = 0.0f;
    g_g[tid] = 0.0f; g_g[tid + 128] = 0.0f;
    __syncthreads();
    if (tid == 0) {
        float l0 = bd2[0] + sp0[0] + sp0[1] + sp0[2] + sp0[3];
        float l1 = bd2[1] + sp1[0] + sp1[1] + sp1[2] + sp1[3];
        float m  = fmaxf(l0, l1);
        float e0 = __expf(l0 - m);
        float e1 = __expf(l1 - m);
        float inv = 1.0f / (e0 + e1);
        out[0] = e0 * inv;
        out[1] = e1 * inv;
        g_sum_s = 0.0f;
        g_c5 = 0u; g_c7 = 0u;
    }
}

// ---------------------------------------------------------------------------
extern "C" void kernel_launch(void* const* d_in, const int* in_sizes, int n_in,
                              void* d_out, int out_size) {
    const float* X   = (const float*)d_in[0];
    const int*   ei  = (const int*)  d_in[1];
    const float* w   = (const float*)d_in[2];
    const float* W1  = (const float*)d_in[3];
    const float* b1  = (const float*)d_in[4];
    const float* W2  = (const float*)d_in[5];
    const float* b2  = (const float*)d_in[6];
    const float* Wd1 = (const float*)d_in[7];
    const float* bd1 = (const float*)d_in[8];
    const float* Wd2 = (const float*)d_in[9];
    const float* bd2 = (const float*)d_in[10];
    float* out = (float*)d_out;

    int n = in_sizes[0] / DIN;        // 20000
    int e = in_sizes[2];              // 640000
    const int* row = ei;
    const int* col = ei + e;
    int chunk = (n + NBLK - 1) / NBLK;

    k_main<<<NBLK, NTHR>>>(X, row, col, w, e, n, chunk);
    k_ug  <<<32,   256>>>(W1, W2, b1);
    k_zf  <<<32,   128>>>(Wd1, b2, bd1, Wd2, bd2, out, 1.0f / (float)n);
}

// round 15
// speedup vs baseline: 1.0477x; 1.0336x over previous
#include <cuda_runtime.h>

#define MAXN 20000
#define DIN  128
#define DHID 256
#define DDNS 128
#define NBLK 304          // 152 SMs x 2 CTAs -> fully resident
#define NTHR 256
#define REP  8            // accumulator replication factor (R11-measured best)

// Persistent scratch. RED accumulators are zero at module load; each run
// re-zeroes what it dirties AFTER last consumption -> replays see clean state.
__device__ float  g_de[REP][MAXN];      // RED: degree (replicated)
__device__ float  g_se[REP][MAXN];      // RED: s edge part (replicated)
__device__ float  g_te[REP][MAXN];      // RED: t edge part (replicated)
__device__ float  g_di[MAXN];           // plain stores (N1)
__device__ float  g_q [MAXN];           // plain stores (N2)
__device__ float2 g_coef[MAXN];         // plain stores (N2)
__device__ float  g_ypart[NBLK][DIN];   // plain stores (P4)
__device__ float  g_sum_s;              // RED (N2), zeroed by k_zf
__device__ float  g_u[DHID];            // RED, zeroed by k_zf
__device__ float  g_g[DHID];            // RED, zeroed by k_zf
__device__ float  g_z[DDNS];            // RED, zeroed by k_zf
__device__ unsigned g_count;            // barrier count (self-resetting)
__device__ volatile unsigned g_gen;     // barrier generation (monotonic ok)
__device__ volatile unsigned g_c5, g_c7;  // tail counters, zeroed by k_zf

// Grid barrier: arrival via one atomic per CTA; WAIT is a volatile load spin
// (L2 read, no RMW serialization). All NBLK CTAs resident by construction.
__device__ __forceinline__ void grid_sync() {
    __syncthreads();
    if (threadIdx.x == 0) {
        unsigned gen = g_gen;
        __threadfence();
        if (atomicAdd(&g_count, 1u) == NBLK - 1u) {
            g_count = 0u;
            __threadfence();
            g_gen = gen + 1u;                  // volatile release store
        } else {
            while (g_gen == gen) __nanosleep(32);
            __threadfence();
        }
    }
    __syncthreads();
}

__device__ __forceinline__ void tail_arrive(volatile unsigned* c) {
    __syncthreads();
    if (threadIdx.x == 0) { __threadfence(); atomicAdd((unsigned*)c, 1u); }
}
__device__ __forceinline__ void tail_wait(volatile unsigned* c, unsigned target) {
    if (threadIdx.x == 0) {
        while (*c < target) __nanosleep(32);
        __threadfence();
    }
    __syncthreads();
}

// ---------------------------------------------------------------------------
__global__ void __launch_bounds__(NTHR, 2)
k_main(const float* __restrict__ X,
       const int* __restrict__ row, const int* __restrict__ col,
       const float* __restrict__ w, int e, int n, int chunk) {
    const int tid    = threadIdx.x;
    const int bid    = blockIdx.x;
    const int rep    = bid & (REP - 1);
    const int t0     = bid * NTHR + tid;
    const int stride = NBLK * NTHR;

    __shared__ float st[128];
    __shared__ float sacc[2][DIN];
    __shared__ float sred[8];

    // ---- P1: de[rep][c] += w ----
    for (int i = t0; i < e; i += stride)
        atomicAdd(&g_de[rep][col[i]], w[i]);
    grid_sync();

    // ---- N1: di = rsqrt(1 + sum(de)); zero de replicas ----
    for (int i = t0; i < n; i += stride) {
        float de = 0.0f;
        #pragma unroll
        for (int r = 0; r < REP; r++) { de += g_de[r][i]; g_de[r][i] = 0.0f; }
        g_di[i] = rsqrtf(1.0f + de);
    }
    grid_sync();

    // ---- P2: se[rep][r] += w * di[c]  (unroll 2 for MLP) ----
    {
        int i = t0;
        for (; i + stride < e; i += 2 * stride) {
            int   c0 = col[i],          c1 = col[i + stride];
            int   r0 = row[i],          r1 = row[i + stride];
            float w0 = w[i],            w1 = w[i + stride];
            float d0 = __ldg(&g_di[c0]);
            float d1 = __ldg(&g_di[c1]);
            atomicAdd(&g_se[rep][r0], w0 * d0);
            atomicAdd(&g_se[rep][r1], w1 * d1);
        }
        if (i < e)
            atomicAdd(&g_se[rep][row[i]], w[i] * __ldg(&g_di[col[i]]));
    }
    grid_sync();

    // ---- N2: s = di*se + di^2; q = di*s; coef = (di^2*s, di); sum_s;
    //      zero se replicas ----
    {
        float ssum = 0.0f;
        for (int i = t0; i < n; i += stride) {
            float se = 0.0f;
            #pragma unroll
            for (int r = 0; r < REP; r++) { se += g_se[r][i]; g_se[r][i] = 0.0f; }
            float di = g_di[i];
            float s  = di * se + di * di;
            g_q[i]    = di * s;
            g_coef[i] = make_float2(di * di * s, di);
            ssum += s;
        }
        int lane = tid & 31, wd = tid >> 5;
        #pragma unroll
        for (int o = 16; o > 0; o >>= 1) ssum += __shfl_down_sync(0xffffffffu, ssum, o);
        if (lane == 0) sred[wd] = ssum;
        __syncthreads();
        if (wd == 0) {
            float v = (lane < 8) ? sred[lane] : 0.0f;
            #pragma unroll
            for (int o = 4; o > 0; o >>= 1) v += __shfl_down_sync(0xffffffffu, v, o);
            if (lane == 0 && v != 0.0f) atomicAdd(&g_sum_s, v);
        }
    }
    grid_sync();

    // ---- P3: te[rep][r] += w * q[c]  (unroll 2) ----
    {
        int i = t0;
        for (; i + stride < e; i += 2 * stride) {
            int   c0 = col[i],          c1 = col[i + stride];
            int   r0 = row[i],          r1 = row[i + stride];
            float w0 = w[i],            w1 = w[i + stride];
            float q0 = __ldg(&g_q[c0]);
            float q1 = __ldg(&g_q[c1]);
            atomicAdd(&g_te[rep][r0], w0 * q0);
            atomicAdd(&g_te[rep][r1], w1 * q1);
        }
        if (i < e)
            atomicAdd(&g_te[rep][row[i]], w[i] * __ldg(&g_q[col[i]]));
    }
    grid_sync();

    // ---- P4: y_part = X^T t over this block's rows; zero te replicas ----
    {
        const int d    = tid & 127;
        const int half = tid >> 7;
        const int start = bid * chunk;
        const int end   = min(n, start + chunk);

        float acc = 0.0f;
        for (int base = start; base < end; base += 128) {
            int m = min(128, end - base);
            __syncthreads();
            if (tid < m) {
                int r = base + tid;
                float te = 0.0f;
                #pragma unroll
                for (int k = 0; k < REP; k++) { te += g_te[k][r]; g_te[k][r] = 0.0f; }
                float2 cf = g_coef[r];
                st[tid] = cf.y * te + cf.x;
            }
            __syncthreads();
            #pragma unroll 8
            for (int k = half; k < m; k += 2)
                acc += st[k] * __ldg(X + (size_t)(base + k) * DIN + d);
        }
        sacc[half][d] = acc;
        __syncthreads();
        if (tid < DIN)
            g_ypart[bid][tid] = sacc[0][tid] + sacc[1][tid];
    }

    // Signal PDL successor (k_ug) that this block's results are committed.
    cudaTriggerProgrammaticLaunchCompletion();
}

// ---------------------------------------------------------------------------
// k_ug (32 blocks x 256): PDL secondary of k_main. Blocks 0..15 do
// u[j] = sum_d y[d]*W1[d,j]; internal counter; then all 32 blocks do
// g[j] += sum_k (u[k]+ss*b1[k])*W2[k,j].
__global__ void __launch_bounds__(256) k_ug(const float* __restrict__ W1,
                                            const float* __restrict__ W2,
                                            const float* __restrict__ b1) {
    // Wait until k_main's grid has fully committed g_ypart/g_sum_s.
    cudaGridDependencySynchronize();

    __shared__ float svec[8];
    int tid = threadIdx.x;
    int bid = blockIdx.x;
    int lane = tid & 31, wd = tid >> 5;

    if (bid < 16) {
        int d0 = bid * 8;
        {
            float v = 0.0f;
            for (int b = lane; b < NBLK; b += 32) v += g_ypart[b][d0 + wd];
            #pragma unroll
            for (int o = 16; o > 0; o >>= 1) v += __shfl_down_sync(0xffffffffu, v, o);
            if (lane == 0) svec[wd] = v;
        }
        __syncthreads();
        float p = 0.0f;
        #pragma unroll
        for (int d = 0; d < 8; d++)
            p += svec[d] * __ldg(&W1[(d0 + d) * DHID + tid]);
        atomicAdd(&g_u[tid], p);
        tail_arrive(&g_c5);
    }
    tail_wait(&g_c5, 16);
    __syncthreads();

    int k0 = bid * 8;
    if (tid < 8) svec[tid] = g_u[k0 + tid] + g_sum_s * __ldg(&b1[k0 + tid]);
    __syncthreads();
    float p = 0.0f;
    #pragma unroll
    for (int k = 0; k < 8; k++)
        p += svec[k] * __ldg(&W2[(k0 + k) * DHID + tid]);
    atomicAdd(&g_g[tid], p);

    cudaTriggerProgrammaticLaunchCompletion();
}

// k_zf (32 blocks x 128): PDL secondary of k_ug. z-accum; counter; block 0
// does relu+logits+softmax and re-zeroes all small scratch + counters.
__global__ void __launch_bounds__(128) k_zf(const float* __restrict__ Wd1,
                                            const float* __restrict__ b2,
                                            const float* __restrict__ bd1,
                                            const float* __restrict__ Wd2,
                                            const float* __restrict__ bd2,
                                            float* __restrict__ out, float invn) {
    cudaGridDependencySynchronize();

    __shared__ float svec[8];
    __shared__ float sp0[4], sp1[4];
    int tid = threadIdx.x;
    int bid = blockIdx.x;
    int lane = tid & 31, wd = tid >> 5;

    {
        int j0 = bid * 8;
        if (tid < 8) svec[tid] = g_g[j0 + tid] * invn + __ldg(&b2[j0 + tid]);
        __syncthreads();
        float p = 0.0f;
        #pragma unroll
        for (int j = 0; j < 8; j++)
            p += svec[j] * __ldg(&Wd1[(j0 + j) * DDNS + tid]);
        atomicAdd(&g_z[tid], p);
    }
    tail_arrive(&g_c7);
    if (bid >= 1) return;
    tail_wait(&g_c7, 32);

    {
        float zr = g_z[tid] + bd1[tid];
        g_z[tid] = 0.0f;
        float z  = zr > 0.0f ? zr : 0.0f;
        float p0 = z * __ldg(&Wd2[tid * 2 + 0]);
        float p1 = z * __ldg(&Wd2[tid * 2 + 1]);
        #pragma unroll
        for (int o = 16; o > 0; o >>= 1) {
            p0 += __shfl_down_sync(0xffffffffu, p0, o);
            p1 += __shfl_down_sync(0xffffffffu, p1, o);
        }
        if (lane == 0) { sp0[wd] = p0; sp1[wd] = p1; }
    }
    g_u[tid] = 0.0f; g_u[tid + 128] = 0.0f;
    g_g[tid] = 0.0f; g_g[tid + 128] = 0.0f;
    __syncthreads();
    if (tid == 0) {
        float l0 = bd2[0] + sp0[0] + sp0[1] + sp0[2] + sp0[3];
        float l1 = bd2[1] + sp1[0] + sp1[1] + sp1[2] + sp1[3];
        float m  = fmaxf(l0, l1);
        float e0 = __expf(l0 - m);
        float e1 = __expf(l1 - m);
        float inv = 1.0f / (e0 + e1);
        out[0] = e0 * inv;
        out[1] = e1 * inv;
        g_sum_s = 0.0f;
        g_c5 = 0u; g_c7 = 0u;
    }
}

// ---------------------------------------------------------------------------
extern "C" void kernel_launch(void* const* d_in, const int* in_sizes, int n_in,
                              void* d_out, int out_size) {
    const float* X   = (const float*)d_in[0];
    const int*   ei  = (const int*)  d_in[1];
    const float* w   = (const float*)d_in[2];
    const float* W1  = (const float*)d_in[3];
    const float* b1  = (const float*)d_in[4];
    const float* W2  = (const float*)d_in[5];
    const float* b2  = (const float*)d_in[6];
    const float* Wd1 = (const float*)d_in[7];
    const float* bd1 = (const float*)d_in[8];
    const float* Wd2 = (const float*)d_in[9];
    const float* bd2 = (const float*)d_in[10];
    float* out = (float*)d_out;

    int n = in_sizes[0] / DIN;        // 20000
    int e = in_sizes[2];              // 640000
    const int* row = ei;
    const int* col = ei + e;
    int chunk = (n + NBLK - 1) / NBLK;
    float invn = 1.0f / (float)n;

    k_main<<<NBLK, NTHR>>>(X, row, col, w, e, n, chunk);

    // Tail kernels launch with programmatic dependency: their launch ramps
    // overlap the predecessor's drain; cudaGridDependencySynchronize() inside
    // guarantees correctness.
    cudaLaunchAttribute attrs[1];
    attrs[0].id = cudaLaunchAttributeProgrammaticStreamSerialization;
    attrs[0].val.programmaticStreamSerializationAllowed = 1;

    {
        cudaLaunchConfig_t cfg = {};
        cfg.gridDim  = dim3(32, 1, 1);
        cfg.blockDim = dim3(256, 1, 1);
        cfg.dynamicSmemBytes = 0;
        cfg.stream = 0;
        cfg.attrs = attrs;
        cfg.numAttrs = 1;
        cudaLaunchKernelEx(&cfg, k_ug, W1, W2, b1);
    }
    {
        cudaLaunchConfig_t cfg = {};
        cfg.gridDim  = dim3(32, 1, 1);
        cfg.blockDim = dim3(128, 1, 1);
        cfg.dynamicSmemBytes = 0;
        cfg.stream = 0;
        cfg.attrs = attrs;
        cfg.numAttrs = 1;
        cudaLaunchKernelEx(&cfg, k_zf, Wd1, b2, bd1, Wd2, bd2, out, invn);
    }
}

// round 16
// speedup vs baseline: 1.1057x; 1.0553x over previous
#include <cuda_runtime.h>

#define MAXN 20000
#define DIN  128
#define DHID 256
#define DDNS 128
#define NBLK 304          // 152 SMs x 2 CTAs -> fully resident
#define NTHR 256
#define REP  8            // accumulator replication factor (measured best)

// Persistent scratch. RED accumulators are zero at module load; each run
// re-zeroes what it dirties AFTER last consumption -> replays see clean state.
__device__ float  g_de[REP][MAXN];      // RED: degree (replicated)
__device__ float  g_se[REP][MAXN];      // RED: s edge part (replicated)
__device__ float  g_te[REP][MAXN];      // RED: t edge part (replicated)
__device__ float  g_di[MAXN];           // plain stores (N1)
__device__ float  g_q [MAXN];           // plain stores (N2)
__device__ float2 g_coef[MAXN];         // plain stores (N2)
__device__ float  g_y[DIN];             // RED (P4), read+zeroed by k_tail
__device__ float  g_sum_s;              // RED (N2), read+zeroed by k_tail
__device__ unsigned g_count;            // barrier count (self-resetting)
__device__ volatile unsigned g_gen;     // barrier generation (monotonic ok)

// Grid barrier: arrival via one atomic per CTA; WAIT is a volatile load spin
// (L2 read, no RMW serialization). All NBLK CTAs resident by construction.
__device__ __forceinline__ void grid_sync() {
    __syncthreads();
    if (threadIdx.x == 0) {
        unsigned gen = g_gen;
        __threadfence();
        if (atomicAdd(&g_count, 1u) == NBLK - 1u) {
            g_count = 0u;
            __threadfence();
            g_gen = gen + 1u;                  // volatile release store
        } else {
            while (g_gen == gen) __nanosleep(32);
            __threadfence();
        }
    }
    __syncthreads();
}

// ---------------------------------------------------------------------------
__global__ void __launch_bounds__(NTHR, 2)
k_main(const float* __restrict__ X,
       const int* __restrict__ row, const int* __restrict__ col,
       const float* __restrict__ w, int e, int n, int chunk) {
    const int tid    = threadIdx.x;
    const int bid    = blockIdx.x;
    const int rep    = bid & (REP - 1);
    const int t0     = bid * NTHR + tid;
    const int stride = NBLK * NTHR;

    __shared__ float st[128];
    __shared__ float sacc[2][DIN];
    __shared__ float sred[8];

    // ---- P1: de[rep][c] += w ----
    for (int i = t0; i < e; i += stride)
        atomicAdd(&g_de[rep][col[i]], w[i]);
    grid_sync();

    // ---- N1: di = rsqrt(1 + sum(de)); zero de replicas ----
    for (int i = t0; i < n; i += stride) {
        float de = 0.0f;
        #pragma unroll
        for (int r = 0; r < REP; r++) { de += g_de[r][i]; g_de[r][i] = 0.0f; }
        g_di[i] = rsqrtf(1.0f + de);
    }
    grid_sync();

    // ---- P2: se[rep][r] += w * di[c]  (unroll 2 for MLP) ----
    {
        int i = t0;
        for (; i + stride < e; i += 2 * stride) {
            int   c0 = col[i],          c1 = col[i + stride];
            int   r0 = row[i],          r1 = row[i + stride];
            float w0 = w[i],            w1 = w[i + stride];
            float d0 = __ldg(&g_di[c0]);
            float d1 = __ldg(&g_di[c1]);
            atomicAdd(&g_se[rep][r0], w0 * d0);
            atomicAdd(&g_se[rep][r1], w1 * d1);
        }
        if (i < e)
            atomicAdd(&g_se[rep][row[i]], w[i] * __ldg(&g_di[col[i]]));
    }
    grid_sync();

    // ---- N2: s = di*se + di^2; q = di*s; coef = (di^2*s, di); sum_s;
    //      zero se replicas ----
    {
        float ssum = 0.0f;
        for (int i = t0; i < n; i += stride) {
            float se = 0.0f;
            #pragma unroll
            for (int r = 0; r < REP; r++) { se += g_se[r][i]; g_se[r][i] = 0.0f; }
            float di = g_di[i];
            float s  = di * se + di * di;
            g_q[i]    = di * s;
            g_coef[i] = make_float2(di * di * s, di);
            ssum += s;
        }
        int lane = tid & 31, wd = tid >> 5;
        #pragma unroll
        for (int o = 16; o > 0; o >>= 1) ssum += __shfl_down_sync(0xffffffffu, ssum, o);
        if (lane == 0) sred[wd] = ssum;
        __syncthreads();
        if (wd == 0) {
            float v = (lane < 8) ? sred[lane] : 0.0f;
            #pragma unroll
            for (int o = 4; o > 0; o >>= 1) v += __shfl_down_sync(0xffffffffu, v, o);
            if (lane == 0 && v != 0.0f) atomicAdd(&g_sum_s, v);
        }
    }
    grid_sync();

    // ---- P3: te[rep][r] += w * q[c]  (unroll 2) ----
    {
        int i = t0;
        for (; i + stride < e; i += 2 * stride) {
            int   c0 = col[i],          c1 = col[i + stride];
            int   r0 = row[i],          r1 = row[i + stride];
            float w0 = w[i],            w1 = w[i + stride];
            float q0 = __ldg(&g_q[c0]);
            float q1 = __ldg(&g_q[c1]);
            atomicAdd(&g_te[rep][r0], w0 * q0);
            atomicAdd(&g_te[rep][r1], w1 * q1);
        }
        if (i < e)
            atomicAdd(&g_te[rep][row[i]], w[i] * __ldg(&g_q[col[i]]));
    }
    grid_sync();

    // ---- P4: y += X^T t over this block's rows (direct RED to g_y);
    //      zero te replicas ----
    {
        const int d    = tid & 127;
        const int half = tid >> 7;
        const int start = bid * chunk;
        const int end   = min(n, start + chunk);

        float acc = 0.0f;
        for (int base = start; base < end; base += 128) {
            int m = min(128, end - base);
            __syncthreads();
            if (tid < m) {
                int r = base + tid;
                float te = 0.0f;
                #pragma unroll
                for (int k = 0; k < REP; k++) { te += g_te[k][r]; g_te[k][r] = 0.0f; }
                float2 cf = g_coef[r];
                st[tid] = cf.y * te + cf.x;
            }
            __syncthreads();
            #pragma unroll 8
            for (int k = half; k < m; k += 2)
                acc += st[k] * __ldg(X + (size_t)(base + k) * DIN + d);
        }
        sacc[half][d] = acc;
        __syncthreads();
        if (tid < DIN)
            atomicAdd(&g_y[tid], sacc[0][tid] + sacc[1][tid]);
    }

    cudaTriggerProgrammaticLaunchCompletion();
}

// ---------------------------------------------------------------------------
// k_tail: ONE block x 1024 threads, zero cross-CTA sync. All stages in smem:
//   u[j]  = sum_d y[d]*W1[d,j] + sum_s*b1[j]            (4 chunks of 32 d)
//   gg[j] = (sum_k u[k]*W2[k,j])/n + b2[j]              (4 chunks of 64 k)
//   z[i]  = relu(sum_j gg[j]*Wd1[j,i] + bd1[i])         (8 chunks of 32 j)
//   out   = softmax(z*Wd2 + bd2)
// Reads + re-zeroes g_y and g_sum_s for the next replay.
__global__ void __launch_bounds__(1024, 1)
k_tail(const float* __restrict__ W1,  const float* __restrict__ b1,
       const float* __restrict__ W2,  const float* __restrict__ b2,
       const float* __restrict__ Wd1, const float* __restrict__ bd1,
       const float* __restrict__ Wd2, const float* __restrict__ bd2,
       float* __restrict__ out, float invn) {
    cudaGridDependencySynchronize();

    __shared__ float sy[DIN];
    __shared__ float spart[8][DHID];     // stage partials (A:4x256, B:4x256, C:8x128)
    __shared__ float su[DHID];
    __shared__ float sg[DHID];
    __shared__ float sz[DDNS];
    __shared__ float sss;
    __shared__ float sp0[4], sp1[4];

    const int tid = threadIdx.x;

    // load y + sum_s; immediately re-zero for next replay
    if (tid < DIN) { sy[tid] = g_y[tid]; g_y[tid] = 0.0f; }
    if (tid == 0)  { sss = g_sum_s; g_sum_s = 0.0f; }
    __syncthreads();

    // ---- Stage A: u[j] ----
    {
        int q = tid >> 8;                // 0..3
        int j = tid & 255;
        const float* W1q = W1 + (q * 32) * DHID + j;
        const float* yq  = sy + q * 32;
        float p = 0.0f;
        #pragma unroll
        for (int d = 0; d < 32; d++)
            p += yq[d] * __ldg(W1q + d * DHID);
        spart[q][j] = p;
    }
    __syncthreads();
    if (tid < DHID)
        su[tid] = spart[0][tid] + spart[1][tid] + spart[2][tid] + spart[3][tid]
                + sss * __ldg(&b1[tid]);
    __syncthreads();

    // ---- Stage B: gg[j] ----
    {
        int q = tid >> 8;                // 0..3
        int j = tid & 255;
        const float* W2q = W2 + (q * 64) * DHID + j;
        const float* uq  = su + q * 64;
        float p = 0.0f;
        #pragma unroll
        for (int k = 0; k < 64; k++)
            p += uq[k] * __ldg(W2q + k * DHID);
        spart[q + 4][j] = p;             // use rows 4..7 (su already consumed? no — su read above, spart rows 0..3 free too; rows 4..7 avoid WAR with stage A reduce)
    }
    __syncthreads();
    if (tid < DHID)
        sg[tid] = (spart[4][tid] + spart[5][tid] + spart[6][tid] + spart[7][tid]) * invn
                + __ldg(&b2[tid]);
    __syncthreads();

    // ---- Stage C: z[i] ----
    {
        int q = tid >> 7;                // 0..7
        int i = tid & 127;
        const float* Wd1q = Wd1 + (q * 32) * DDNS + i;
        const float* gq   = sg + q * 32;
        float p = 0.0f;
        #pragma unroll
        for (int j = 0; j < 32; j++)
            p += gq[j] * __ldg(Wd1q + j * DDNS);
        spart[q][i] = p;                 // 8 x 128 partials (cols 0..127)
    }
    __syncthreads();
    if (tid < DDNS) {
        float zr = spart[0][tid] + spart[1][tid] + spart[2][tid] + spart[3][tid]
                 + spart[4][tid] + spart[5][tid] + spart[6][tid] + spart[7][tid]
                 + __ldg(&bd1[tid]);
        sz[tid] = zr > 0.0f ? zr : 0.0f;
    }
    __syncthreads();

    // ---- Stage D: logits + softmax ----
    if (tid < DDNS) {
        float z  = sz[tid];
        float p0 = z * __ldg(&Wd2[tid * 2 + 0]);
        float p1 = z * __ldg(&Wd2[tid * 2 + 1]);
        int lane = tid & 31, wd = tid >> 5;
        #pragma unroll
        for (int o = 16; o > 0; o >>= 1) {
            p0 += __shfl_down_sync(0xffffffffu, p0, o);
            p1 += __shfl_down_sync(0xffffffffu, p1, o);
        }
        if (lane == 0) { sp0[wd] = p0; sp1[wd] = p1; }
    }
    __syncthreads();
    if (tid == 0) {
        float l0 = __ldg(&bd2[0]) + sp0[0] + sp0[1] + sp0[2] + sp0[3];
        float l1 = __ldg(&bd2[1]) + sp1[0] + sp1[1] + sp1[2] + sp1[3];
        float m  = fmaxf(l0, l1);
        float e0 = __expf(l0 - m);
        float e1 = __expf(l1 - m);
        float inv = 1.0f / (e0 + e1);
        out[0] = e0 * inv;
        out[1] = e1 * inv;
    }
}

// ---------------------------------------------------------------------------
extern "C" void kernel_launch(void* const* d_in, const int* in_sizes, int n_in,
                              void* d_out, int out_size) {
    const float* X   = (const float*)d_in[0];
    const int*   ei  = (const int*)  d_in[1];
    const float* w   = (const float*)d_in[2];
    const float* W1  = (const float*)d_in[3];
    const float* b1  = (const float*)d_in[4];
    const float* W2  = (const float*)d_in[5];
    const float* b2  = (const float*)d_in[6];
    const float* Wd1 = (const float*)d_in[7];
    const float* bd1 = (const float*)d_in[8];
    const float* Wd2 = (const float*)d_in[9];
    const float* bd2 = (const float*)d_in[10];
    float* out = (float*)d_out;

    int n = in_sizes[0] / DIN;        // 20000
    int e = in_sizes[2];              // 640000
    const int* row = ei;
    const int* col = ei + e;
    int chunk = (n + NBLK - 1) / NBLK;
    float invn = 1.0f / (float)n;

    k_main<<<NBLK, NTHR>>>(X, row, col, w, e, n, chunk);

    // PDL: tail's launch ramp overlaps k_main's drain; the
    // cudaGridDependencySynchronize() inside guarantees correctness.
    cudaLaunchAttribute attrs[1];
    attrs[0].id = cudaLaunchAttributeProgrammaticStreamSerialization;
    attrs[0].val.programmaticStreamSerializationAllowed = 1;

    cudaLaunchConfig_t cfg = {};
    cfg.gridDim  = dim3(1, 1, 1);
    cfg.blockDim = dim3(1024, 1, 1);
    cfg.dynamicSmemBytes = 0;
    cfg.stream = 0;
    cfg.attrs = attrs;
    cfg.numAttrs = 1;
    cudaLaunchKernelEx(&cfg, k_tail, W1, b1, W2, b2, Wd1, bd1, Wd2, bd2,
                       out, invn);
}